// round 12
// baseline (speedup 1.0000x reference)
#include <cuda_runtime.h>
#include <cuda_bf16.h>
#include <cstdint>

// ---------------- problem constants ----------------
#define BS      2
#define C_IN    64
#define NA      60
#define KS      3
#define ANN     8
#define C_OUT   128
#define K_DIM   192              // C_IN*KS
#define NPAIRS  180              // NA*KS
#define NP      1024
#define NJOBS   (BS * NP)        // 2048

#define NTHREADS 256
#define GRID_CTAS 444            // 3 per SM x 148 SMs

#define KSTEPS  12               // stage-B ksteps (192/16)
#define NTILES  8                // stage-B ntiles (64/8)
#define KSA     4                // stage-A ksteps (64/16)
#define MTA     12               // stage-A mtiles (192/16)

// ---------------- SMEM layout (bytes) ----------------
#define B_BYTES     (NTILES * KSTEPS * 32 * 16)      // 49152
#define SMEM_B      0
#define FF_BYTES    (NTILES * KSA * 32 * 16)         // 16384
#define SMEM_FF     B_BYTES
#define SMEM_TOTAL  (SMEM_FF + FF_BYTES)             // 65536 (x3 = 196608 <= 228KB)

// ---------------- global fragment tables ----------------
// W fragments: [part hi/lo][mtile 8][kstep 12][lane 32][4 x b32]
__device__ __align__(16) uint32_t Afrag_g[2 * 8 * KSTEPS * 32 * 4];   // 96 KB
// M fragments (gather matrix): [part][mtile 12][kstep 4][lane 32][4 x b32]
__device__ __align__(16) uint32_t Mfrag_g[2 * MTA * KSA * 32 * 4];    // 48 KB

// ---------------- prep: pack W and M fragments ----------------
__global__ void pack_frags_kernel(const float* __restrict__ Wmat,
                                  const float* __restrict__ intra_w,
                                  const int*   __restrict__ intra_idx)
{
    const int t = blockIdx.x * 256 + threadIdx.x;
    const int NW = 2 * 8 * KSTEPS * 32;              // 6144
    const int NM = 2 * MTA * KSA * 32;               // 3072

    if (t < NW) {
        const int lane = t & 31;
        const int ks   = (t >> 5) % KSTEPS;
        const int mt   = (t >> 5) / KSTEPS % 8;
        const int part = t / (32 * KSTEPS * 8);
        const int r0 = mt * 16 + (lane >> 2);
        const int k0 = ks * 16 + ((lane & 3) << 1);
        uint32_t regs[4];
        #pragma unroll
        for (int reg = 0; reg < 4; reg++) {
            const int r = r0 + ((reg & 1) ? 8 : 0);
            const int k = k0 + ((reg & 2) ? 8 : 0);
            float f0 = Wmat[r * K_DIM + k];
            float f1 = Wmat[r * K_DIM + k + 1];
            __nv_bfloat16 h0 = __float2bfloat16_rn(f0);
            __nv_bfloat16 h1 = __float2bfloat16_rn(f1);
            __nv_bfloat16 v0, v1;
            if (part == 0) { v0 = h0; v1 = h1; }
            else {
                v0 = __float2bfloat16_rn(f0 - __bfloat162float(h0));
                v1 = __float2bfloat16_rn(f1 - __bfloat162float(h1));
            }
            regs[reg] = (uint32_t)__bfloat16_as_ushort(v0) |
                        ((uint32_t)__bfloat16_as_ushort(v1) << 16);
        }
        *(uint4*)(Afrag_g + (size_t)t * 4) = make_uint4(regs[0], regs[1], regs[2], regs[3]);
    } else if (t < NW + NM) {
        const int tm = t - NW;
        const int lane = tm & 31;
        const int ks   = (tm >> 5) % KSA;
        const int mt   = (tm >> 5) / KSA % MTA;
        const int part = tm / (32 * KSA * MTA);
        const int r0 = mt * 16 + (lane >> 2);
        const int j0 = ks * 16 + ((lane & 3) << 1);
        uint32_t regs[4];
        #pragma unroll
        for (int reg = 0; reg < 4; reg++) {
            const int r = r0 + ((reg & 1) ? 8 : 0);
            const int j = j0 + ((reg & 2) ? 8 : 0);
            float v0 = 0.f, v1 = 0.f;
            if (r < NPAIRS) {
                #pragma unroll
                for (int a = 0; a < ANN; a++) {
                    const int   id = intra_idx[r * ANN + a];
                    const float wv = intra_w[r * ANN + a];
                    if (id == j)     v0 += wv;
                    if (id == j + 1) v1 += wv;
                }
            }
            __nv_bfloat16 h0 = __float2bfloat16_rn(v0);
            __nv_bfloat16 h1 = __float2bfloat16_rn(v1);
            __nv_bfloat16 o0, o1;
            if (part == 0) { o0 = h0; o1 = h1; }
            else {
                o0 = __float2bfloat16_rn(v0 - __bfloat162float(h0));
                o1 = __float2bfloat16_rn(v1 - __bfloat162float(h1));
            }
            regs[reg] = (uint32_t)__bfloat16_as_ushort(o0) |
                        ((uint32_t)__bfloat16_as_ushort(o1) << 16);
        }
        *(uint4*)(Mfrag_g + (size_t)tm * 4) = make_uint4(regs[0], regs[1], regs[2], regs[3]);
    }
}

// stage-B B-frag byte offset for logical (o = n index, kc = k index)
__device__ __forceinline__ uint32_t bfrag_off32(int o, int kc) {
    const uint32_t u = (uint32_t)((((o >> 3) * KSTEPS + (kc >> 4)) * 32) +
                                  ((o & 7) << 2) + ((kc >> 1) & 3));
    return (u << 4) + ((((uint32_t)kc >> 3) & 1) << 3) + (((uint32_t)kc & 1) << 2);
}
// stage-A feats-frag byte offset for logical (c = n index, j = k index)
__device__ __forceinline__ uint32_t ffrag_off32(int c, int j) {
    const uint32_t u = (uint32_t)((((c >> 3) * KSA + (j >> 4)) * 32) +
                                  ((c & 7) << 2) + ((j >> 1) & 3));
    return (u << 4) + ((((uint32_t)j >> 3) & 1) << 3) + (((uint32_t)j & 1) << 2);
}

__device__ __forceinline__ uint32_t smem_u32(const void* p) {
    uint32_t a;
    asm("{ .reg .u64 t; cvta.to.shared.u64 t, %1; cvt.u32.u64 %0, t; }" : "=r"(a) : "l"(p));
    return a;
}

__device__ __forceinline__ void mma_bf16(float* c, const uint4 a, uint32_t b0, uint32_t b1) {
    asm volatile(
        "mma.sync.aligned.m16n8k16.row.col.f32.bf16.bf16.f32 "
        "{%0,%1,%2,%3}, {%4,%5,%6,%7}, {%8,%9}, {%0,%1,%2,%3};"
        : "+f"(c[0]), "+f"(c[1]), "+f"(c[2]), "+f"(c[3])
        : "r"(a.x), "r"(a.y), "r"(a.z), "r"(a.w), "r"(b0), "r"(b1));
}

__device__ __forceinline__ uint32_t pack_hl(float x) {
    const __nv_bfloat16 h = __float2bfloat16_rn(x);
    const __nv_bfloat16 l = __float2bfloat16_rn(x - __bfloat162float(h));
    return (uint32_t)__bfloat16_as_ushort(h) | ((uint32_t)__bfloat16_as_ushort(l) << 16);
}

// ---------------- main fused kernel (persistent, 3 CTAs/SM) ----------------
__global__ __launch_bounds__(NTHREADS, 3)
void intrazp_mma_kernel(const float* __restrict__ feats,
                        const float* __restrict__ bias,
                        float* __restrict__ out)
{
    extern __shared__ char smem[];
    const uint32_t smb = smem_u32(smem);
    const int tid = threadIdx.x, wid = tid >> 5, lane = tid & 31;
    const int mq = wid & 3, nq = wid >> 2;

    // zero FF buffer once (pad K slots j>=60 stay zero forever)
    for (int t = tid; t < FF_BYTES / 16; t += NTHREADS)
        ((uint4*)(smem + SMEM_FF))[t] = make_uint4(0, 0, 0, 0);

    // bias for stage-B accumulators
    const int rb = mq * 32 + (lane >> 2);
    float bv[4];
    #pragma unroll
    for (int i = 0; i < 4; i++) bv[i] = __ldg(bias + rb + i * 8);
    __syncthreads();

    for (int job = blockIdx.x; job < NJOBS; job += GRID_CTAS) {
        const int b = job >> 10, p = job & (NP - 1);

        // ---- phase 0: feats -> stage-A B fragments (split bf16 hi|lo) ----
        for (int t = tid; t < C_IN * 15; t += NTHREADS) {
            const int c = t / 15, q = t - c * 15;
            const float4 v = __ldg((const float4*)(feats +
                              (((size_t)b * C_IN + c) * NP + p) * NA) + q);
            const int j = q * 4;
            asm volatile("st.shared.u32 [%0], %1;"
                         :: "r"(smb + SMEM_FF + ffrag_off32(c, j)),     "r"(pack_hl(v.x)));
            asm volatile("st.shared.u32 [%0], %1;"
                         :: "r"(smb + SMEM_FF + ffrag_off32(c, j + 1)), "r"(pack_hl(v.y)));
            asm volatile("st.shared.u32 [%0], %1;"
                         :: "r"(smb + SMEM_FF + ffrag_off32(c, j + 2)), "r"(pack_hl(v.z)));
            asm volatile("st.shared.u32 [%0], %1;"
                         :: "r"(smb + SMEM_FF + ffrag_off32(c, j + 3)), "r"(pack_hl(v.w)));
        }
        __syncthreads();

        // ---- stage A: C1[192 ok x 64 c] = M @ feats^T (3-pass split) ----
        // warp tile: 3 mtiles x 4 ntiles, processed in 2 ntile-chunks of 2
        // (keeps accumulators at 24 regs for the 3-CTA occupancy budget).
        #pragma unroll
        for (int ch = 0; ch < 2; ch++) {
            float acc1[3][2][4];
            #pragma unroll
            for (int i = 0; i < 3; i++)
                #pragma unroll
                for (int j = 0; j < 2; j++)
                    acc1[i][j][0] = acc1[i][j][1] = acc1[i][j][2] = acc1[i][j][3] = 0.f;

            #pragma unroll
            for (int ks = 0; ks < KSA; ks++) {
                uint4 ah[3], al[3];
                #pragma unroll
                for (int i = 0; i < 3; i++) {
                    const int mt = mq * 3 + i;
                    ah[i] = __ldg((const uint4*)Mfrag_g + ((0   + mt) * KSA + ks) * 32 + lane);
                    al[i] = __ldg((const uint4*)Mfrag_g + ((MTA + mt) * KSA + ks) * 32 + lane);
                }
                #pragma unroll
                for (int j = 0; j < 2; j++) {
                    const int nt = nq * 4 + ch * 2 + j;
                    uint32_t g0, g1, g2, g3;
                    asm volatile("ld.shared.v4.b32 {%0,%1,%2,%3}, [%4];"
                                 : "=r"(g0), "=r"(g1), "=r"(g2), "=r"(g3)
                                 : "r"(smb + SMEM_FF + (uint32_t)(((nt * KSA + ks) * 32 + lane) << 4)));
                    uint32_t bh0, bh1, bl0, bl1;
                    asm("prmt.b32 %0, %1, %2, 0x5410;" : "=r"(bh0) : "r"(g0), "r"(g1));
                    asm("prmt.b32 %0, %1, %2, 0x7632;" : "=r"(bl0) : "r"(g0), "r"(g1));
                    asm("prmt.b32 %0, %1, %2, 0x5410;" : "=r"(bh1) : "r"(g2), "r"(g3));
                    asm("prmt.b32 %0, %1, %2, 0x7632;" : "=r"(bl1) : "r"(g2), "r"(g3));
                    #pragma unroll
                    for (int i = 0; i < 3; i++) {
                        mma_bf16(acc1[i][j], ah[i], bh0, bh1);
                        mma_bf16(acc1[i][j], ah[i], bl0, bl1);
                        mma_bf16(acc1[i][j], al[i], bh0, bh1);
                    }
                }
            }

            // scatter chunk -> stage-B B fragments (packed hi|lo)
            #pragma unroll
            for (int i = 0; i < 3; i++) {
                #pragma unroll
                for (int j = 0; j < 2; j++) {
                    const int row0 = (mq * 3 + i) * 16 + (lane >> 2);
                    const int col0 = (nq * 4 + ch * 2 + j) * 8 + (lane & 3) * 2;
                    #pragma unroll
                    for (int e = 0; e < 4; e++) {
                        const int row = row0 + ((e >> 1) << 3);   // ok
                        const int col = col0 + (e & 1);           // c
                        const int o  = row / 3;
                        const int kk = row - o * 3;
                        asm volatile("st.shared.u32 [%0], %1;"
                                     :: "r"(smb + SMEM_B + bfrag_off32(o, col * 3 + kk)),
                                        "r"(pack_hl(acc1[i][j][e])));
                    }
                }
            }
        }
        __syncthreads();

        // ---- stage B: out[128 x 64] = W @ v (3-pass split), warp 32M x 32N ----
        float acc[2][4][4];
        #pragma unroll
        for (int mt = 0; mt < 2; mt++)
            #pragma unroll
            for (int j = 0; j < 4; j++) {
                acc[mt][j][0] = bv[2 * mt];     acc[mt][j][1] = bv[2 * mt];
                acc[mt][j][2] = bv[2 * mt + 1]; acc[mt][j][3] = bv[2 * mt + 1];
            }

        const int mt0 = 2 * mq;
        #pragma unroll 4
        for (int ks = 0; ks < KSTEPS; ks++) {
            uint4 ah[2], al[2];
            #pragma unroll
            for (int mt = 0; mt < 2; mt++) {
                ah[mt] = __ldg((const uint4*)Afrag_g + ((0 + mt0 + mt) * KSTEPS + ks) * 32 + lane);
                al[mt] = __ldg((const uint4*)Afrag_g + ((8 + mt0 + mt) * KSTEPS + ks) * 32 + lane);
            }
            #pragma unroll
            for (int j = 0; j < 4; j++) {
                const int nt = nq * 4 + j;
                uint32_t g0, g1, g2, g3;
                asm volatile("ld.shared.v4.b32 {%0,%1,%2,%3}, [%4];"
                             : "=r"(g0), "=r"(g1), "=r"(g2), "=r"(g3)
                             : "r"(smb + SMEM_B + (uint32_t)(((nt * KSTEPS + ks) * 32 + lane) << 4)));
                uint32_t bh0, bh1, bl0, bl1;
                asm("prmt.b32 %0, %1, %2, 0x5410;" : "=r"(bh0) : "r"(g0), "r"(g1));
                asm("prmt.b32 %0, %1, %2, 0x7632;" : "=r"(bl0) : "r"(g0), "r"(g1));
                asm("prmt.b32 %0, %1, %2, 0x5410;" : "=r"(bh1) : "r"(g2), "r"(g3));
                asm("prmt.b32 %0, %1, %2, 0x7632;" : "=r"(bl1) : "r"(g2), "r"(g3));
                #pragma unroll
                for (int mt = 0; mt < 2; mt++) {
                    mma_bf16(acc[mt][j], ah[mt], bh0, bh1);   // hi*hi
                    mma_bf16(acc[mt][j], ah[mt], bl0, bl1);   // hi*lo
                    mma_bf16(acc[mt][j], al[mt], bh0, bh1);   // lo*hi
                }
            }
        }

        // ---- epilogue ----
        {
            const int ncol = nq * 32 + (lane & 3) * 2;
            #pragma unroll
            for (int mt = 0; mt < 2; mt++) {
                const int r1 = mq * 32 + mt * 16 + (lane >> 2);
                float* orow1 = out + (((size_t)(b * C_OUT + r1)) * NP + p) * NA;
                float* orow2 = orow1 + (size_t)8 * NP * NA;
                #pragma unroll
                for (int j = 0; j < 4; j++) {
                    const int n = ncol + j * 8;
                    if (n < NA) {
                        *(float2*)(orow1 + n) = make_float2(acc[mt][j][0], acc[mt][j][1]);
                        *(float2*)(orow2 + n) = make_float2(acc[mt][j][2], acc[mt][j][3]);
                    }
                }
            }
        }
        __syncthreads();   // protect fragment buffers before next job
    }
}

extern "C" void kernel_launch(void* const* d_in, const int* in_sizes, int n_in,
                              void* d_out, int out_size)
{
    const float* feats     = (const float*)d_in[0];  // (2,64,1024,60) f32
    const float* intra_w   = (const float*)d_in[1];  // (60,3,8)       f32
    const float* Wmat      = (const float*)d_in[2];  // (128,192)      f32
    const float* bias      = (const float*)d_in[3];  // (1,128,1)      f32
    const int*   intra_idx = (const int*)  d_in[4];  // (60,3,8)       i32
    float* out = (float*)d_out;                      // (2,128,1024,60) f32

    cudaFuncSetAttribute(intrazp_mma_kernel,
                         cudaFuncAttributeMaxDynamicSharedMemorySize, SMEM_TOTAL);

    pack_frags_kernel<<<(2 * 8 * KSTEPS * 32 + 2 * MTA * KSA * 32 + 255) / 256, 256>>>(
        Wmat, intra_w, intra_idx);
    intrazp_mma_kernel<<<GRID_CTAS, NTHREADS, SMEM_TOTAL>>>(feats, bias, out);
}

// round 13
// speedup vs baseline: 1.2234x; 1.2234x over previous
#include <cuda_runtime.h>
#include <cuda_bf16.h>
#include <cstdint>

// ---------------- problem constants ----------------
#define BS      2
#define C_IN    64
#define NA      60
#define KS      3
#define ANN     8
#define C_OUT   128
#define K_DIM   192              // C_IN*KS
#define NPAIRS  180              // NA*KS
#define NP      1024
#define NJOBS   (BS * NP)        // 2048

#define NTHREADS 256
#define GRID_CTAS 444            // 3 per SM x 148 SMs

#define KPAIRS  12               // 192 / 16 (two k8 steps per iteration)
#define NTILES  8                // 64 / 8

// ---------------- SMEM layout (bytes) ----------------
// B fragments (tf32 f32): 16B unit u = (nt*KPAIRS + kp)*32 + lane holds
//   [0]=b0(ks even) [4]=b1(ks even) [8]=b0(ks odd) [12]=b1(ks odd)
#define B_BYTES     (NTILES * KPAIRS * 32 * 16)      // 49152
#define SMEM_B      0
#define FPAD        61
#define SMEM_F      B_BYTES                          // 49152
#define SMEM_IDX    (SMEM_F + C_IN * FPAD * 4)       // 64768 (16B aligned)
#define SMEM_WV     (SMEM_IDX + NPAIRS * ANN * 4)    // 70528
#define SMEM_TOTAL  (SMEM_WV + NPAIRS * ANN * 4)     // 76288 (x3 = 228864 <= 228KB)

// ---------------- A fragments (W) in tf32 m16n8k8 per-lane order ----------------
// [mtile 8][kpair 12][lane 32][2 x uint4]  (uint4 h: a0..a3 for ks = kp*2+h)
__device__ __align__(16) uint32_t Afrag_g[8 * KPAIRS * 32 * 8];   // 96 KB

__global__ void pack_W_kernel(const float* __restrict__ Wmat) {
    int t = blockIdx.x * 256 + threadIdx.x;          // t = (mt*12+kp)*32+lane
    if (t >= 8 * KPAIRS * 32) return;
    const int lane = t & 31;
    const int kp   = (t >> 5) % KPAIRS;
    const int mt   = (t >> 5) / KPAIRS;
    const int r0 = mt * 16 + (lane >> 2);
    #pragma unroll
    for (int h = 0; h < 2; h++) {
        const int k0 = kp * 16 + h * 8 + (lane & 3);
        uint32_t regs[4];
        #pragma unroll
        for (int reg = 0; reg < 4; reg++) {
            const int r = r0 + ((reg & 1) ? 8 : 0);
            const int k = k0 + ((reg & 2) ? 4 : 0);
            const float f = Wmat[r * K_DIM + k];
            asm("cvt.rna.tf32.f32 %0, %1;" : "=r"(regs[reg]) : "f"(f));
        }
        *(uint4*)(Afrag_g + ((size_t)t * 2 + h) * 4) =
            make_uint4(regs[0], regs[1], regs[2], regs[3]);
    }
}

// byte offset of the f32 for logical (o = n index, kc = k index)
__device__ __forceinline__ uint32_t bfrag_off32(int o, int kc) {
    const uint32_t u = (uint32_t)((((o >> 3) * KPAIRS + (kc >> 4)) * 32) +
                                  ((o & 7) << 2) + (kc & 3));
    return (u << 4) + ((((uint32_t)kc >> 3) & 1) << 3) + (((uint32_t)kc >> 2) & 1) * 4;
}

__device__ __forceinline__ uint32_t smem_u32(const void* p) {
    uint32_t a;
    asm("{ .reg .u64 t; cvta.to.shared.u64 t, %1; cvt.u32.u64 %0, t; }" : "=r"(a) : "l"(p));
    return a;
}

__device__ __forceinline__ void mma_tf32(float* c, const uint4 a, uint32_t b0, uint32_t b1) {
    asm volatile(
        "mma.sync.aligned.m16n8k8.row.col.f32.tf32.tf32.f32 "
        "{%0,%1,%2,%3}, {%4,%5,%6,%7}, {%8,%9}, {%0,%1,%2,%3};"
        : "+f"(c[0]), "+f"(c[1]), "+f"(c[2]), "+f"(c[3])
        : "r"(a.x), "r"(a.y), "r"(a.z), "r"(a.w), "r"(b0), "r"(b1));
}

// ---------------- main fused kernel (persistent, 3 CTAs/SM) ----------------
__global__ __launch_bounds__(NTHREADS, 3)
void intrazp_mma_kernel(const float* __restrict__ feats,
                        const float* __restrict__ intra_w,
                        const float* __restrict__ bias,
                        const int*   __restrict__ intra_idx,
                        float* __restrict__ out)
{
    extern __shared__ char smem[];
    const uint32_t smb = smem_u32(smem);
    float* Fsm  = (float*)(smem + SMEM_F);
    int*   Ism  = (int*)  (smem + SMEM_IDX);
    float* Wvsm = (float*)(smem + SMEM_WV);
    const int tid = threadIdx.x, wid = tid >> 5, lane = tid & 31;

    // warp tiling for GEMM: 4M x 2N; warp covers rows [32*mq, +32), cols [32*nq, +32)
    const int mq = wid & 3, nq = wid >> 2;

    // ---- one-time: zero B pad rows (o = 60..63), cache idx/w in smem ----
    for (int t = tid; t < 4 * K_DIM; t += NTHREADS) {
        const int o = 60 + t / K_DIM, kc = t % K_DIM;
        asm volatile("st.shared.u32 [%0], %1;"
                     :: "r"(smb + SMEM_B + bfrag_off32(o, kc)), "r"(0u));
    }
    for (int t = tid; t < NPAIRS * ANN; t += NTHREADS) {
        Ism[t]  = __ldg(intra_idx + t);
        Wvsm[t] = __ldg(intra_w + t);
    }

    // bias for the 4 row-groups this thread accumulates
    const int rb = mq * 32 + (lane >> 2);
    float bv[4];
    #pragma unroll
    for (int i = 0; i < 4; i++) bv[i] = __ldg(bias + rb + i * 8);
    __syncthreads();

    for (int job = blockIdx.x; job < NJOBS; job += GRID_CTAS) {
        const int b = job >> 10, p = job & (NP - 1);

        // ---- load feats slab (64 x 60) as float4 ----
        for (int t = tid; t < C_IN * 15; t += NTHREADS) {
            const int c = t / 15, q = t - c * 15;
            const float4 v = __ldg((const float4*)(feats +
                              (((size_t)b * C_IN + c) * NP + p) * NA) + q);
            float* dst = Fsm + c * FPAD + q * 4;
            dst[0] = v.x; dst[1] = v.y; dst[2] = v.z; dst[3] = v.w;
        }
        __syncthreads();

        // ---- stage A: gather-reduce -> tf32 B fragments ----
        for (int pr = wid; pr < NPAIRS; pr += 8) {
            const int o = pr / KS, kk = pr - o * KS;
            const int4   ia = *(const int4*)  (Ism  + pr * ANN);
            const int4   ib = *((const int4*) (Ism  + pr * ANN) + 1);
            const float4 wa = *(const float4*)(Wvsm + pr * ANN);
            const float4 wb = *((const float4*)(Wvsm + pr * ANN) + 1);
            #pragma unroll
            for (int half = 0; half < 2; half++) {
                const int c = half * 32 + lane;
                const float* fr = Fsm + c * FPAD;
                float acc = fr[ia.x] * wa.x;
                acc = fmaf(fr[ia.y], wa.y, acc);
                acc = fmaf(fr[ia.z], wa.z, acc);
                acc = fmaf(fr[ia.w], wa.w, acc);
                acc = fmaf(fr[ib.x], wb.x, acc);
                acc = fmaf(fr[ib.y], wb.y, acc);
                acc = fmaf(fr[ib.z], wb.z, acc);
                acc = fmaf(fr[ib.w], wb.w, acc);
                uint32_t tv;
                asm("cvt.rna.tf32.f32 %0, %1;" : "=r"(tv) : "f"(acc));
                asm volatile("st.shared.u32 [%0], %1;"
                             :: "r"(smb + SMEM_B + bfrag_off32(o, c * KS + kk)), "r"(tv));
            }
        }
        __syncthreads();

        // ---- GEMM: single-pass TF32, warp tile 32M x 32N ----
        float acc[2][4][4];
        #pragma unroll
        for (int mt = 0; mt < 2; mt++)
            #pragma unroll
            for (int j = 0; j < 4; j++) {
                acc[mt][j][0] = bv[2 * mt];     acc[mt][j][1] = bv[2 * mt];
                acc[mt][j][2] = bv[2 * mt + 1]; acc[mt][j][3] = bv[2 * mt + 1];
            }

        const int mt0 = 2 * mq;
        #pragma unroll 4
        for (int kp = 0; kp < KPAIRS; kp++) {
            uint4 a0[2], a1[2];      // per mtile: ks even / ks odd
            #pragma unroll
            for (int mt = 0; mt < 2; mt++) {
                const uint4* ap = (const uint4*)Afrag_g +
                                  (((mt0 + mt) * KPAIRS + kp) * 32 + lane) * 2;
                a0[mt] = __ldg(ap);
                a1[mt] = __ldg(ap + 1);
            }
            #pragma unroll
            for (int j = 0; j < 4; j++) {
                const int nt = nq * 4 + j;
                uint32_t g0, g1, g2, g3;   // b0/b1 even, b0/b1 odd
                asm volatile("ld.shared.v4.b32 {%0,%1,%2,%3}, [%4];"
                             : "=r"(g0), "=r"(g1), "=r"(g2), "=r"(g3)
                             : "r"(smb + SMEM_B + (uint32_t)(((nt * KPAIRS + kp) * 32 + lane) << 4)));
                #pragma unroll
                for (int mt = 0; mt < 2; mt++) {
                    mma_tf32(acc[mt][j], a0[mt], g0, g1);   // ks even
                    mma_tf32(acc[mt][j], a1[mt], g2, g3);   // ks odd
                }
            }
        }

        // ---- epilogue: store rows (2 mtiles x 2 row-groups), cols 32*nq..+31 ----
        {
            const int ncol = nq * 32 + (lane & 3) * 2;
            #pragma unroll
            for (int mt = 0; mt < 2; mt++) {
                const int r1 = mq * 32 + mt * 16 + (lane >> 2);
                float* orow1 = out + (((size_t)(b * C_OUT + r1)) * NP + p) * NA;
                float* orow2 = orow1 + (size_t)8 * NP * NA;
                #pragma unroll
                for (int j = 0; j < 4; j++) {
                    const int n = ncol + j * 8;
                    if (n < NA) {
                        *(float2*)(orow1 + n) = make_float2(acc[mt][j][0], acc[mt][j][1]);
                        *(float2*)(orow2 + n) = make_float2(acc[mt][j][2], acc[mt][j][3]);
                    }
                }
            }
        }
        __syncthreads();   // protect Fsm/B before next job
    }
}

extern "C" void kernel_launch(void* const* d_in, const int* in_sizes, int n_in,
                              void* d_out, int out_size)
{
    const float* feats     = (const float*)d_in[0];  // (2,64,1024,60) f32
    const float* intra_w   = (const float*)d_in[1];  // (60,3,8)       f32
    const float* Wmat      = (const float*)d_in[2];  // (128,192)      f32
    const float* bias      = (const float*)d_in[3];  // (1,128,1)      f32
    const int*   intra_idx = (const int*)  d_in[4];  // (60,3,8)       i32
    float* out = (float*)d_out;                      // (2,128,1024,60) f32

    cudaFuncSetAttribute(intrazp_mma_kernel,
                         cudaFuncAttributeMaxDynamicSharedMemorySize, SMEM_TOTAL);

    pack_W_kernel<<<(8 * KPAIRS * 32 + 255) / 256, 256>>>(Wmat);
    intrazp_mma_kernel<<<GRID_CTAS, NTHREADS, SMEM_TOTAL>>>(
        feats, intra_w, bias, intra_idx, out);
}

// round 15
// speedup vs baseline: 1.7506x; 1.4309x over previous
#include <cuda_runtime.h>
#include <cuda_fp16.h>
#include <cstdint>

// ---------------- problem constants ----------------
#define BS      2
#define C_IN    64
#define NA      60
#define KS      3
#define ANN     8
#define C_OUT   128
#define K_DIM   192              // C_IN*KS
#define NPAIRS  180              // NA*KS
#define NP      1024
#define NJOBS   (BS * NP)        // 2048

#define NTHREADS 256
#define GRID_CTAS 444            // 3 per SM x 148 SMs

#define KSTEPS  12               // 192 / 16
#define NTILES  8                // 64 / 8

// ---------------- SMEM layout (bytes) ----------------
// B fragments (fp16): unit (nt,ks,lane) = 8B {b0: k0,k0+1 | b1: k0+8,k0+9}
#define B_BYTES     (NTILES * KSTEPS * 32 * 8)       // 24576
#define SMEM_B      0
// feats slab as packed half2(c, c+32): [cp 32][61 u32]
#define FPADH       61
#define SMEM_FH     B_BYTES                          // 24576
#define FH_BYTES    (32 * FPADH * 4)                 // 7808
#define SMEM_IDX    (SMEM_FH + FH_BYTES)             // 32384 (16B aligned)
#define SMEM_WV     (SMEM_IDX + NPAIRS * ANN * 4)    // 38144
#define SMEM_TOTAL  (SMEM_WV + NPAIRS * ANN * 4)     // 43904 (x3 = 131712)

// ---------------- A fragments (W, fp16) in m16n8k16 per-lane order ----------------
// [mtile 8][kstep 12][lane 32][4 x b32]  -> 48 KB (L1-resident)
__device__ __align__(16) uint32_t Afrag_g[8 * KSTEPS * 32 * 4];

__global__ void pack_W_kernel(const float* __restrict__ Wmat) {
    int t = blockIdx.x * 256 + threadIdx.x;          // t = (mt*12+ks)*32+lane
    if (t >= 8 * KSTEPS * 32) return;
    const int lane = t & 31;
    const int ks   = (t >> 5) % KSTEPS;
    const int mt   = (t >> 5) / KSTEPS;
    const int r0 = mt * 16 + (lane >> 2);
    const int k0 = ks * 16 + ((lane & 3) << 1);
    uint32_t regs[4];
    #pragma unroll
    for (int reg = 0; reg < 4; reg++) {
        const int r = r0 + ((reg & 1) ? 8 : 0);
        const int k = k0 + ((reg & 2) ? 8 : 0);
        const __half h0 = __float2half_rn(Wmat[r * K_DIM + k]);
        const __half h1 = __float2half_rn(Wmat[r * K_DIM + k + 1]);
        regs[reg] = (uint32_t)__half_as_ushort(h0) |
                    ((uint32_t)__half_as_ushort(h1) << 16);
    }
    *(uint4*)(Afrag_g + (size_t)t * 4) = make_uint4(regs[0], regs[1], regs[2], regs[3]);
}

// byte offset of the u16 for logical (o = n index, kc = k index)
__device__ __forceinline__ uint32_t bfrag_off16(int o, int kc) {
    const uint32_t blane = (uint32_t)(((o & 7) << 2) | ((kc >> 1) & 3));
    const uint32_t unit  = (uint32_t)(((o >> 3) * KSTEPS + (kc >> 4)) * 32) + blane;
    return (unit << 3) + ((((uint32_t)kc >> 3) & 1) << 2) + (((uint32_t)kc & 1) << 1);
}

__device__ __forceinline__ uint32_t smem_u32(const void* p) {
    uint32_t a;
    asm("{ .reg .u64 t; cvta.to.shared.u64 t, %1; cvt.u32.u64 %0, t; }" : "=r"(a) : "l"(p));
    return a;
}

__device__ __forceinline__ void mma_f16(float* c, const uint4 a, uint32_t b0, uint32_t b1) {
    asm volatile(
        "mma.sync.aligned.m16n8k16.row.col.f32.f16.f16.f32 "
        "{%0,%1,%2,%3}, {%4,%5,%6,%7}, {%8,%9}, {%0,%1,%2,%3};"
        : "+f"(c[0]), "+f"(c[1]), "+f"(c[2]), "+f"(c[3])
        : "r"(a.x), "r"(a.y), "r"(a.z), "r"(a.w), "r"(b0), "r"(b1));
}

// bit-cast a packed u32 (two fp16) to float2
__device__ __forceinline__ float2 u32_to_float2(uint32_t w) {
    const __half2 h2 = *reinterpret_cast<const __half2*>(&w);
    return __half22float2(h2);
}

// ---------------- main fused kernel (persistent, 3 CTAs/SM) ----------------
__global__ __launch_bounds__(NTHREADS, 3)
void intrazp_mma_kernel(const float* __restrict__ feats,
                        const float* __restrict__ intra_w,
                        const float* __restrict__ bias,
                        const int*   __restrict__ intra_idx,
                        float* __restrict__ out)
{
    extern __shared__ char smem[];
    const uint32_t smb = smem_u32(smem);
    uint32_t* FsmH = (uint32_t*)(smem + SMEM_FH);    // [cp][61], half2(c, c+32)
    int*   Ism  = (int*)  (smem + SMEM_IDX);
    float* Wvsm = (float*)(smem + SMEM_WV);
    const int tid = threadIdx.x, wid = tid >> 5, lane = tid & 31;

    // warp tiling for GEMM: 4M x 2N
    const int mq = wid & 3, nq = wid >> 2;

    // ---- one-time: zero B pad rows (o = 60..63), cache idx/w in smem ----
    for (int t = tid; t < 4 * K_DIM; t += NTHREADS) {
        const int o = 60 + t / K_DIM, kc = t % K_DIM;
        asm volatile("st.shared.u16 [%0], %1;"
                     :: "r"(smb + SMEM_B + bfrag_off16(o, kc)), "h"((unsigned short)0));
    }
    for (int t = tid; t < NPAIRS * ANN; t += NTHREADS) {
        Ism[t]  = __ldg(intra_idx + t);
        Wvsm[t] = __ldg(intra_w + t);
    }

    // bias for the 4 row-groups this thread accumulates
    const int rb = mq * 32 + (lane >> 2);
    float bv[4];
    #pragma unroll
    for (int i = 0; i < 4; i++) bv[i] = __ldg(bias + rb + i * 8);
    __syncthreads();

    for (int job = blockIdx.x; job < NJOBS; job += GRID_CTAS) {
        const int b = job >> 10, p = job & (NP - 1);

        // ---- load feats: rows c and c+32, pack into half2 slab ----
        for (int t = tid; t < 32 * 15; t += NTHREADS) {
            const int c = t / 15, q = t - c * 15;
            const float* base = feats + (((size_t)b * C_IN + c) * NP + p) * NA;
            const float4 v0 = __ldg((const float4*)base + q);
            const float4 v1 = __ldg((const float4*)(base + (size_t)32 * NP * NA) + q);
            uint32_t* dst = FsmH + c * FPADH + q * 4;
            dst[0] = (uint32_t)__half_as_ushort(__float2half_rn(v0.x)) |
                     ((uint32_t)__half_as_ushort(__float2half_rn(v1.x)) << 16);
            dst[1] = (uint32_t)__half_as_ushort(__float2half_rn(v0.y)) |
                     ((uint32_t)__half_as_ushort(__float2half_rn(v1.y)) << 16);
            dst[2] = (uint32_t)__half_as_ushort(__float2half_rn(v0.z)) |
                     ((uint32_t)__half_as_ushort(__float2half_rn(v1.z)) << 16);
            dst[3] = (uint32_t)__half_as_ushort(__float2half_rn(v0.w)) |
                     ((uint32_t)__half_as_ushort(__float2half_rn(v1.w)) << 16);
        }
        __syncthreads();

        // ---- stage A: gather-reduce (both c-halves per LDS.32) -> fp16 B frags ----
        for (int pr = wid; pr < NPAIRS; pr += 8) {
            const int o = pr / KS, kk = pr - o * KS;
            const int4   ia = *(const int4*)  (Ism  + pr * ANN);
            const int4   ib = *((const int4*) (Ism  + pr * ANN) + 1);
            const float4 wa = *(const float4*)(Wvsm + pr * ANN);
            const float4 wb = *((const float4*)(Wvsm + pr * ANN) + 1);
            const uint32_t* fr = FsmH + lane * FPADH;
            float a0 = 0.f, a1 = 0.f;
            #pragma unroll
            for (int a = 0; a < ANN; a++) {
                const int   iv = (a < 4) ? ((const int*)&ia)[a]   : ((const int*)&ib)[a - 4];
                const float wv = (a < 4) ? ((const float*)&wa)[a] : ((const float*)&wb)[a - 4];
                const float2 f = u32_to_float2(fr[iv]);
                a0 = fmaf(f.x, wv, a0);
                a1 = fmaf(f.y, wv, a1);
            }
            asm volatile("st.shared.u16 [%0], %1;"
                         :: "r"(smb + SMEM_B + bfrag_off16(o, lane * KS + kk)),
                            "h"(__half_as_ushort(__float2half_rn(a0))));
            asm volatile("st.shared.u16 [%0], %1;"
                         :: "r"(smb + SMEM_B + bfrag_off16(o, (lane + 32) * KS + kk)),
                            "h"(__half_as_ushort(__float2half_rn(a1))));
        }
        __syncthreads();

        // ---- GEMM: single-pass fp16 m16n8k16, warp tile 32M x 32N ----
        float acc[2][4][4];
        #pragma unroll
        for (int mt = 0; mt < 2; mt++)
            #pragma unroll
            for (int j = 0; j < 4; j++) {
                acc[mt][j][0] = bv[2 * mt];     acc[mt][j][1] = bv[2 * mt];
                acc[mt][j][2] = bv[2 * mt + 1]; acc[mt][j][3] = bv[2 * mt + 1];
            }

        const int mt0 = 2 * mq;
        #pragma unroll 4
        for (int ks = 0; ks < KSTEPS; ks++) {
            uint4 af[2];
            #pragma unroll
            for (int mt = 0; mt < 2; mt++)
                af[mt] = __ldg((const uint4*)Afrag_g + ((mt0 + mt) * KSTEPS + ks) * 32 + lane);
            #pragma unroll
            for (int j = 0; j < 4; j++) {
                const int nt = nq * 4 + j;
                uint32_t b0, b1;
                asm volatile("ld.shared.v2.b32 {%0,%1}, [%2];"
                             : "=r"(b0), "=r"(b1)
                             : "r"(smb + SMEM_B + (uint32_t)(((nt * KSTEPS + ks) * 32 + lane) << 3)));
                #pragma unroll
                for (int mt = 0; mt < 2; mt++)
                    mma_f16(acc[mt][j], af[mt], b0, b1);
            }
        }

        // ---- epilogue: store rows (2 mtiles x 2 row-groups), cols 32*nq..+31 ----
        {
            const int ncol = nq * 32 + (lane & 3) * 2;
            #pragma unroll
            for (int mt = 0; mt < 2; mt++) {
                const int r1 = mq * 32 + mt * 16 + (lane >> 2);
                float* orow1 = out + (((size_t)(b * C_OUT + r1)) * NP + p) * NA;
                float* orow2 = orow1 + (size_t)8 * NP * NA;
                #pragma unroll
                for (int j = 0; j < 4; j++) {
                    const int n = ncol + j * 8;
                    if (n < NA) {
                        *(float2*)(orow1 + n) = make_float2(acc[mt][j][0], acc[mt][j][1]);
                        *(float2*)(orow2 + n) = make_float2(acc[mt][j][2], acc[mt][j][3]);
                    }
                }
            }
        }
        __syncthreads();   // protect FsmH/B before next job
    }
}

extern "C" void kernel_launch(void* const* d_in, const int* in_sizes, int n_in,
                              void* d_out, int out_size)
{
    const float* feats     = (const float*)d_in[0];  // (2,64,1024,60) f32
    const float* intra_w   = (const float*)d_in[1];  // (60,3,8)       f32
    const float* Wmat      = (const float*)d_in[2];  // (128,192)      f32
    const float* bias      = (const float*)d_in[3];  // (1,128,1)      f32
    const int*   intra_idx = (const int*)  d_in[4];  // (60,3,8)       i32
    float* out = (float*)d_out;                      // (2,128,1024,60) f32

    cudaFuncSetAttribute(intrazp_mma_kernel,
                         cudaFuncAttributeMaxDynamicSharedMemorySize, SMEM_TOTAL);

    pack_W_kernel<<<(8 * KSTEPS * 32 + 255) / 256, 256>>>(Wmat);
    intrazp_mma_kernel<<<GRID_CTAS, NTHREADS, SMEM_TOTAL>>>(
        feats, intra_w, bias, intra_idx, out);
}